// round 12
// baseline (speedup 1.0000x reference)
#include <cuda_runtime.h>
#include <cuda_bf16.h>
#include <cstdint>
#include <cstddef>

#define B_DIM   16384
#define IN_DIM  512
#define OUT_DIM 512
#define ORDER   10
#define K_TOT   (IN_DIM + IN_DIM * ORDER)   /* 5632 */

// W scratch (11.5 MB, L2-resident): [OUT][K_TOT] tf32-rounded rows.
__device__ float g_W[(size_t)OUT_DIM * K_TOT];

__device__ __forceinline__ float to_tf32(float x) {
    float r;
    asm("cvt.rna.tf32.f32 %0, %1;" : "=f"(r) : "f"(x));
    return r;
}

// ---------------------------------------------------------------------------
// Phase 0: pack W[n,0:512]=base_weight[n,:], W[n,512:5632]=cheby_weight[n,:,:]
// (the (OUT, IN*O) reshape is a pure view of the contiguous (OUT,IN,O) tensor).
// ---------------------------------------------------------------------------
__global__ void build_W_kernel(const float* __restrict__ bw,
                               const float* __restrict__ cw) {
    const int row_f4 = K_TOT / 4;  // 1408 float4 per row
    int idx = blockIdx.x * blockDim.x + threadIdx.x;
    if (idx >= OUT_DIM * row_f4) return;
    int n = idx / row_f4;
    int k = (idx - n * row_f4) * 4;
    float4 v;
    if (k < IN_DIM) {
        v = __ldg((const float4*)(bw + (size_t)n * IN_DIM + k));
    } else {
        v = __ldg((const float4*)(cw + (size_t)n * (IN_DIM * ORDER) + (k - IN_DIM)));
    }
    v.x = to_tf32(v.x); v.y = to_tf32(v.y); v.z = to_tf32(v.z); v.w = to_tf32(v.w);
    *(float4*)(g_W + (size_t)n * K_TOT + k) = v;
}

// ---------------------------------------------------------------------------
// Fused GEMM: C[16384,512] = A(x)[16384,5632] @ W[512,5632]^T, mma.sync tf32.
// A generated on the fly. For C-row b, K-tile kt (BK=32): sgm = kt>>4.
//   sgm==0: A[b, col] = silu(x[b, col])
//   sgm>=1: o2=sgm-1, m=10*b+o2, o=m>>14, b'=m&16383,
//           A[b, col] = 0.1 * T_o(x[b', col-512*sgm])  (exact reshape inverse)
// CTA tile 128x64, 256 threads = 8 warps (4x2) of 32x32; acc 32 regs/thread
// -> __launch_bounds__(256,3) gives 3 CTAs/SM (24 warps, 37.5% occ).
// BK=32 halves barrier count vs the 929us baseline (176 iters, 2 syncs each).
// Smem rows padded to 36 floats: (4*gid+tg)%32 covers all banks.
// ---------------------------------------------------------------------------
#define BM 128
#define BN 64
#define BK 32
#define LDSS 36                          /* floats per smem row (144B) */
#define A_FLOATS (BM * LDSS)             /* 4608 */
#define STAGE_FLOATS ((BM + BN) * LDSS)  /* 6912 floats = 27648 B */
#define SMEM_BYTES (2 * STAGE_FLOATS * 4)/* 55296 B */
#define NTHREADS 256
#define NKT (K_TOT / BK)                 /* 176 */

__device__ __forceinline__ void cp_async16(unsigned dst, const void* src) {
    asm volatile("cp.async.cg.shared.global [%0], [%1], 16;" :: "r"(dst), "l"(src));
}

__device__ __forceinline__ float4 a_val(float4 xv, int o) {
    float4 r;
    if (o < 0) {                      // silu
        r.x = xv.x / (1.0f + __expf(-xv.x));
        r.y = xv.y / (1.0f + __expf(-xv.y));
        r.z = xv.z / (1.0f + __expf(-xv.z));
        r.w = xv.w / (1.0f + __expf(-xv.w));
    } else if (o == 0) {              // 0.1 * T_0
        r = make_float4(0.1f, 0.1f, 0.1f, 0.1f);
    } else {                          // 0.1 * T_o
        float4 tm = make_float4(1.f, 1.f, 1.f, 1.f);
        float4 tc = xv;
        for (int j = 2; j <= o; j++) {
            float4 t;
            t.x = 2.0f * xv.x * tc.x - tm.x;
            t.y = 2.0f * xv.y * tc.y - tm.y;
            t.z = 2.0f * xv.z * tc.z - tm.z;
            t.w = 2.0f * xv.w * tc.w - tm.w;
            tm = tc; tc = t;
        }
        r.x = 0.1f * tc.x; r.y = 0.1f * tc.y;
        r.z = 0.1f * tc.z; r.w = 0.1f * tc.w;
    }
    r.x = to_tf32(r.x); r.y = to_tf32(r.y);
    r.z = to_tf32(r.z); r.w = to_tf32(r.w);
    return r;
}

__global__ __launch_bounds__(NTHREADS, 3)
void gemm_fused_kernel(const float* __restrict__ x, float* __restrict__ C) {
    extern __shared__ __align__(16) float sm[];   // 2 stages x [A(128x36)|W(64x36)]

    const int tid  = threadIdx.x;
    const int lane = tid & 31;
    const int wid  = tid >> 5;
    const int wm   = wid >> 1;        // 0..3 -> 32-row slab
    const int wn   = wid & 1;         // 0..1 -> 32-col slab
    const int gid  = lane >> 2;       // 0..7
    const int tg   = lane & 3;        // 0..3

    const int bm = blockIdx.y * BM;
    const int bn = blockIdx.x * BN;

    // A loader: row ar (0..127), half ah -> 16 floats at col ah
    const int ar = tid >> 1;
    const int ah = (tid & 1) << 4;
    // W loader: row wr (0..63), 8 floats at col wc
    const int wr = tid >> 2;
    const int wc = (tid & 3) << 3;

    const float* Wb = g_W + (size_t)(bn + wr) * K_TOT + wc;
    const unsigned sbase = (unsigned)__cvta_generic_to_shared(sm);
    const unsigned wdst0 = sbase + (unsigned)(A_FLOATS + wr * LDSS + wc) * 4u;

    // ---- prologue: tile 0 -> stage 0 ----
    {
        cp_async16(wdst0,       Wb);
        cp_async16(wdst0 + 16u, Wb + 4);
        asm volatile("cp.async.commit_group;");
        // A tile 0 (segment 0 = silu)
        const float4* xp = (const float4*)(x + (size_t)(bm + ar) * IN_DIM + ah);
        float* As = sm + ar * LDSS + ah;
#pragma unroll
        for (int j = 0; j < 4; j++)
            *(float4*)(As + j * 4) = a_val(__ldg(xp + j), -1);
        asm volatile("cp.async.wait_group 0;");
    }
    __syncthreads();

    float acc[2][4][4] = {};
    float4 xr[4];
    int on = 0;

    for (int kt = 0; kt < NKT; kt++) {
        // prefetch tile kt+1: x -> regs, W -> smem stage (kt+1)&1
        if (kt + 1 < NKT) {
            const int nq  = kt + 1;
            const int sgm = nq >> 4;
            const int i0  = ((nq & 15) << 5) + ah;
            int xrow;
            if (sgm == 0) { xrow = bm + ar; on = -1; }
            else { int m = (bm + ar) * 10 + (sgm - 1); on = m >> 14; xrow = m & 16383; }
            const float4* xp = (const float4*)(x + (size_t)xrow * IN_DIM + i0);
#pragma unroll
            for (int j = 0; j < 4; j++) xr[j] = __ldg(xp + j);

            const unsigned soff = (unsigned)((kt + 1) & 1) * (STAGE_FLOATS * 4u);
            const float* Wk = Wb + (size_t)(kt + 1) * BK;
            cp_async16(wdst0 + soff,       Wk);
            cp_async16(wdst0 + soff + 16u, Wk + 4);
            asm volatile("cp.async.commit_group;");
        }

        // MMAs on tile kt
        const float* A_s = sm + (kt & 1) * STAGE_FLOATS;
        const float* W_s = A_s + A_FLOATS;
        const int arow = wm * 32 + gid;
        const int bcol = wn * 32 + gid;

#pragma unroll
        for (int ks = 0; ks < 4; ks++) {
            const int k0 = ks * 8 + tg;
            unsigned a[2][4], b[4][2];
#pragma unroll
            for (int mi = 0; mi < 2; mi++) {
                const float* p = A_s + (arow + mi * 16) * LDSS + k0;
                a[mi][0] = __float_as_uint(p[0]);
                a[mi][1] = __float_as_uint(p[8 * LDSS]);
                a[mi][2] = __float_as_uint(p[4]);
                a[mi][3] = __float_as_uint(p[8 * LDSS + 4]);
            }
#pragma unroll
            for (int ni = 0; ni < 4; ni++) {
                const float* p = W_s + (bcol + ni * 8) * LDSS + k0;
                b[ni][0] = __float_as_uint(p[0]);
                b[ni][1] = __float_as_uint(p[4]);
            }
#pragma unroll
            for (int mi = 0; mi < 2; mi++)
#pragma unroll
                for (int ni = 0; ni < 4; ni++) {
                    asm volatile(
                        "mma.sync.aligned.m16n8k8.row.col.f32.tf32.tf32.f32 "
                        "{%0,%1,%2,%3}, {%4,%5,%6,%7}, {%8,%9}, {%0,%1,%2,%3};"
                        : "+f"(acc[mi][ni][0]), "+f"(acc[mi][ni][1]),
                          "+f"(acc[mi][ni][2]), "+f"(acc[mi][ni][3])
                        : "r"(a[mi][0]), "r"(a[mi][1]), "r"(a[mi][2]), "r"(a[mi][3]),
                          "r"(b[ni][0]), "r"(b[ni][1]));
                }
        }

        // produce A tile kt+1 from prefetched x; land W tile kt+1
        if (kt + 1 < NKT) {
            float* An = sm + ((kt + 1) & 1) * STAGE_FLOATS + ar * LDSS + ah;
#pragma unroll
            for (int j = 0; j < 4; j++)
                *(float4*)(An + j * 4) = a_val(xr[j], on);
            asm volatile("cp.async.wait_group 0;");
        }
        __syncthreads();
    }

    // epilogue: c0,c1 at (row, 2tg), c2,c3 at (row+8, 2tg)
#pragma unroll
    for (int mi = 0; mi < 2; mi++) {
#pragma unroll
        for (int ni = 0; ni < 4; ni++) {
            const int row = bm + wm * 32 + mi * 16 + gid;
            const int col = bn + wn * 32 + ni * 8 + 2 * tg;
            *(float2*)(C + (size_t)row * OUT_DIM + col) =
                make_float2(acc[mi][ni][0], acc[mi][ni][1]);
            *(float2*)(C + (size_t)(row + 8) * OUT_DIM + col) =
                make_float2(acc[mi][ni][2], acc[mi][ni][3]);
        }
    }
}

// ---------------------------------------------------------------------------
extern "C" void kernel_launch(void* const* d_in, const int* in_sizes, int n_in,
                              void* d_out, int out_size) {
    const float* x  = nullptr;
    const float* bw = nullptr;
    const float* cw = nullptr;
    for (int i = 0; i < n_in; i++) {
        if (in_sizes[i] == B_DIM * IN_DIM)                x  = (const float*)d_in[i];
        else if (in_sizes[i] == OUT_DIM * IN_DIM)         bw = (const float*)d_in[i];
        else if (in_sizes[i] == OUT_DIM * IN_DIM * ORDER) cw = (const float*)d_in[i];
    }
    float* out = (float*)d_out;

    {   // phase 0: weight pack (720896 float4)
        int total = OUT_DIM * (K_TOT / 4);
        build_W_kernel<<<(total + 255) / 256, 256>>>(bw, cw);
    }
    {   // phase 1: fused A-gen + tf32 mma.sync GEMM
        cudaFuncSetAttribute(gemm_fused_kernel,
                             cudaFuncAttributeMaxDynamicSharedMemorySize, SMEM_BYTES);
        dim3 grid(OUT_DIM / BN, B_DIM / BM);   // (8, 128)
        gemm_fused_kernel<<<grid, NTHREADS, SMEM_BYTES>>>(x, out);
    }
}

// round 14
// speedup vs baseline: 1.0293x; 1.0293x over previous
#include <cuda_runtime.h>
#include <cuda_bf16.h>
#include <cstdint>
#include <cstddef>

#define B_DIM   16384
#define IN_DIM  512
#define OUT_DIM 512
#define ORDER   10
#define K_TOT   (IN_DIM + IN_DIM * ORDER)   /* 5632 */
#define NKT     (K_TOT / 32)                /* 176 BK=32 chunks */

// W pre-packed in MMA-fragment order (tf32-rounded), 11.5 MB, L2-resident.
// Layout per chunk q (16384 floats): [nb 16][ni 4][ks2 2][lane 32][j 4]
//   value(j) at n = nb*32+ni*8+gid, k = q*32 + (ks2*2+ks_lo)*8 + tg + 4*pair
//   with gid=lane>>2, tg=lane&3, j = ks_lo*2 + pair.
__device__ float g_Wf[(size_t)NKT * 16384];

__device__ __forceinline__ float to_tf32(float x) {
    float r;
    asm("cvt.rna.tf32.f32 %0, %1;" : "=f"(r) : "f"(x));
    return r;
}

// ---------------------------------------------------------------------------
// Phase 0: fragment-pack W. One thread per (q, n, ks2): reads 16 consecutive
// Wcat cols (never straddles the base/cheby boundary: base is 16-aligned),
// transposes into 4 output float4s (one per tg), stores contiguously.
// Wcat[n] = [base_weight[n,:] | cheby_weight[n,:,:]] (reshape is a pure view).
// ---------------------------------------------------------------------------
__global__ void build_W_kernel(const float* __restrict__ bw,
                               const float* __restrict__ cw) {
    int idx = blockIdx.x * blockDim.x + threadIdx.x;
    if (idx >= NKT * 512 * 2) return;
    int ks2 = idx & 1;
    int t   = idx >> 1;
    int n   = t & 511;
    int q   = t >> 9;

    int base = q * 32 + ks2 * 16;     // first of 16 consecutive k-columns
    const float* src;
    if (base < IN_DIM) src = bw + (size_t)n * IN_DIM + base;
    else               src = cw + (size_t)n * (IN_DIM * ORDER) + (base - IN_DIM);

    float4 c0 = __ldg((const float4*)src);        // cols +0..3   (ks_lo0,pair0)
    float4 c1 = __ldg((const float4*)(src + 4));  // +4..7        (ks_lo0,pair1)
    float4 c2 = __ldg((const float4*)(src + 8));  // +8..11       (ks_lo1,pair0)
    float4 c3 = __ldg((const float4*)(src + 12)); // +12..15      (ks_lo1,pair1)

    int gid = n & 7, ni = (n >> 3) & 3, nb = n >> 5;
    float* dst = g_Wf + (size_t)q * 16384 + nb * 1024 + ni * 256 + ks2 * 128 + gid * 16;

    const float* a = &c0.x; const float* b = &c1.x;
    const float* c = &c2.x; const float* d = &c3.x;
#pragma unroll
    for (int tg = 0; tg < 4; tg++) {
        float4 o = make_float4(to_tf32(a[tg]), to_tf32(b[tg]),
                               to_tf32(c[tg]), to_tf32(d[tg]));
        *(float4*)(dst + tg * 4) = o;
    }
}

// ---------------------------------------------------------------------------
// Fused GEMM: C[16384,512] = A(x)[16384,5632] @ W[512,5632]^T, mma.sync tf32.
// R6-proven shape: CTA 128x128, 8 warps (2x4) of 64x32, occ 2. BK=32.
// A generated on the fly (sgm = q>>4; sgm==0 silu; else m=10b+sgm-1,
// o=m>>14, b'=m&16383, 0.1*T_o(x[b',.]) — exact reshape inverse).
// Both A and W live in smem in FRAGMENT order:
//   A: [mi 8][ks 4][lane 32][reg' 4], reg' = c1 + 2*r1 (so producer STS.64
//      pairs are contiguous); consumer LDS.128, mma args = f0,f2,f1,f3.
//   W: [nb_local 4][ni 4][ks2 2][lane 32][j 4]; LDS.128 serves 2 k-steps.
// ---------------------------------------------------------------------------
#define BM 128
#define BN 128
#define NTHREADS 256
#define A_STAGE 16384                 /* bytes */
#define STAGE   32768                 /* bytes: A + W */
#define SMEM_BYTES (2 * STAGE)        /* 64 KB */

__device__ __forceinline__ void cp_async16(unsigned dst, const void* src) {
    asm volatile("cp.async.cg.shared.global [%0], [%1], 16;" :: "r"(dst), "l"(src));
}

__device__ __forceinline__ float4 a_val(float4 xv, int o) {
    float4 r;
    if (o < 0) {
        r.x = xv.x / (1.0f + __expf(-xv.x));
        r.y = xv.y / (1.0f + __expf(-xv.y));
        r.z = xv.z / (1.0f + __expf(-xv.z));
        r.w = xv.w / (1.0f + __expf(-xv.w));
    } else if (o == 0) {
        r = make_float4(0.1f, 0.1f, 0.1f, 0.1f);
    } else {
        float4 tm = make_float4(1.f, 1.f, 1.f, 1.f);
        float4 tc = xv;
        for (int j = 2; j <= o; j++) {
            float4 t;
            t.x = 2.0f * xv.x * tc.x - tm.x;
            t.y = 2.0f * xv.y * tc.y - tm.y;
            t.z = 2.0f * xv.z * tc.z - tm.z;
            t.w = 2.0f * xv.w * tc.w - tm.w;
            tm = tc; tc = t;
        }
        r.x = 0.1f * tc.x; r.y = 0.1f * tc.y;
        r.z = 0.1f * tc.z; r.w = 0.1f * tc.w;
    }
    r.x = to_tf32(r.x); r.y = to_tf32(r.y);
    r.z = to_tf32(r.z); r.w = to_tf32(r.w);
    return r;
}

__global__ __launch_bounds__(NTHREADS, 2)
void gemm_fused_kernel(const float* __restrict__ x, float* __restrict__ C) {
    extern __shared__ __align__(16) char smem[];

    const int tid  = threadIdx.x;
    const int lane = tid & 31;
    const int wid  = tid >> 5;
    const int wm   = wid >> 2;        // 0..1 -> 64-row slab
    const int wn   = wid & 3;         // 0..3 -> 32-col slab
    const int gid  = lane >> 2;
    const int tg   = lane & 3;

    const int bm = blockIdx.y * BM;
    const int bn = blockIdx.x * BN;
    const int bx = blockIdx.x;

    // producer (A-gen): row r, col-half ch (16 cols)
    const int r   = tid >> 1;
    const int ch  = tid & 1;
    const int mip = r >> 4;
    const int gdp = r & 7;
    const int r1p = (r >> 3) & 1;
    // producer STS.64 base (bytes within A stage) for ks = 2*ch + ksl, tg=m:
    //   ((mip*4 + ks)*32 + gdp*4 + m)*16 + r1p*8
    const unsigned sbase = (unsigned)__cvta_generic_to_shared(smem);

    // W cp.async: 4 x 16B per thread, linear
    const unsigned wdst0 = sbase + A_STAGE + (unsigned)tid * 16u;
    const float*  wsrc_b = g_Wf + (size_t)bx * 4096 + (size_t)tid * 4;

    // ---- prologue: chunk 0 -> stage 0 ----
    {
#pragma unroll
        for (int jj = 0; jj < 4; jj++)
            cp_async16(wdst0 + jj * 4096u, wsrc_b + jj * 1024);
        asm volatile("cp.async.commit_group;");

        const float4* xp = (const float4*)(x + (size_t)(bm + r) * IN_DIM + ch * 16);
        float4 v0 = a_val(__ldg(xp), -1),     v1 = a_val(__ldg(xp + 1), -1);
        float4 v2 = a_val(__ldg(xp + 2), -1), v3 = a_val(__ldg(xp + 3), -1);
        const float* pv0 = &v0.x; const float* pv1 = &v1.x;
        const float* pv2 = &v2.x; const float* pv3 = &v3.x;
#pragma unroll
        for (int m = 0; m < 4; m++) {
            unsigned lo = sbase + ((mip * 4 + 2 * ch) * 32 + gdp * 4 + m) * 16u + r1p * 8u;
            unsigned hi = sbase + ((mip * 4 + 2 * ch + 1) * 32 + gdp * 4 + m) * 16u + r1p * 8u;
            asm volatile("st.shared.v2.f32 [%0], {%1,%2};" :: "r"(lo), "f"(pv0[m]), "f"(pv1[m]));
            asm volatile("st.shared.v2.f32 [%0], {%1,%2};" :: "r"(hi), "f"(pv2[m]), "f"(pv3[m]));
        }
        asm volatile("cp.async.wait_group 0;");
    }
    __syncthreads();

    float acc[4][4][4] = {};
    float4 xr0, xr1, xr2, xr3;
    int on = 0;

    for (int kt = 0; kt < NKT; kt++) {
        // prefetch chunk kt+1: x -> regs, W -> smem next stage
        if (kt + 1 < NKT) {
            const int nq  = kt + 1;
            const int sgm = nq >> 4;
            const int i0  = ((nq & 15) << 5) + ch * 16;
            int xrow;
            if (sgm == 0) { xrow = bm + r; on = -1; }
            else { int m = (bm + r) * 10 + (sgm - 1); on = m >> 14; xrow = m & 16383; }
            const float4* xp = (const float4*)(x + (size_t)xrow * IN_DIM + i0);
            xr0 = __ldg(xp); xr1 = __ldg(xp + 1); xr2 = __ldg(xp + 2); xr3 = __ldg(xp + 3);

            const unsigned soff = (unsigned)((kt + 1) & 1) * STAGE;
            const float* ws = g_Wf + (size_t)(kt + 1) * 16384 + bx * 4096 + tid * 4;
#pragma unroll
            for (int jj = 0; jj < 4; jj++)
                cp_async16(wdst0 + soff + jj * 4096u, ws + jj * 1024);
            asm volatile("cp.async.commit_group;");
        }

        // MMAs on stage kt&1
        const unsigned As = sbase + (unsigned)(kt & 1) * STAGE;
        const unsigned Ws = As + A_STAGE;

#pragma unroll
        for (int ks2 = 0; ks2 < 2; ks2++) {
            unsigned bfr[4][4];
#pragma unroll
            for (int ni = 0; ni < 4; ni++) {
                unsigned addr = Ws + (((wn * 4 + ni) * 2 + ks2) * 32 + lane) * 16u;
                asm volatile("ld.shared.v4.b32 {%0,%1,%2,%3}, [%4];"
                    : "=r"(bfr[ni][0]), "=r"(bfr[ni][1]), "=r"(bfr[ni][2]), "=r"(bfr[ni][3])
                    : "r"(addr));
            }
#pragma unroll
            for (int ksl = 0; ksl < 2; ksl++) {
                const int ks = ks2 * 2 + ksl;
                unsigned afr[4][4];
#pragma unroll
                for (int mm = 0; mm < 4; mm++) {
                    unsigned addr = As + (((wm * 4 + mm) * 4 + ks) * 32 + lane) * 16u;
                    asm volatile("ld.shared.v4.b32 {%0,%1,%2,%3}, [%4];"
                        : "=r"(afr[mm][0]), "=r"(afr[mm][1]), "=r"(afr[mm][2]), "=r"(afr[mm][3])
                        : "r"(addr));
                }
#pragma unroll
                for (int mm = 0; mm < 4; mm++)
#pragma unroll
                    for (int ni = 0; ni < 4; ni++) {
                        // a order: f0, f2, f1, f3 (reg' = c1 + 2*r1)
                        // b words: ksl==0 -> (j0, j1); ksl==1 -> (j2, j3)
                        asm volatile(
                            "mma.sync.aligned.m16n8k8.row.col.f32.tf32.tf32.f32 "
                            "{%0,%1,%2,%3}, {%4,%5,%6,%7}, {%8,%9}, {%0,%1,%2,%3};"
                            : "+f"(acc[mm][ni][0]), "+f"(acc[mm][ni][1]),
                              "+f"(acc[mm][ni][2]), "+f"(acc[mm][ni][3])
                            : "r"(afr[mm][0]), "r"(afr[mm][2]),
                              "r"(afr[mm][1]), "r"(afr[mm][3]),
                              "r"(bfr[ni][ksl * 2]), "r"(bfr[ni][ksl * 2 + 1]));
                    }
            }
        }

        // produce A chunk kt+1 into next stage; land W
        if (kt + 1 < NKT) {
            float4 v0 = a_val(xr0, on), v1 = a_val(xr1, on);
            float4 v2 = a_val(xr2, on), v3 = a_val(xr3, on);
            const float* pv0 = &v0.x; const float* pv1 = &v1.x;
            const float* pv2 = &v2.x; const float* pv3 = &v3.x;
            const unsigned An = sbase + (unsigned)((kt + 1) & 1) * STAGE;
#pragma unroll
            for (int m = 0; m < 4; m++) {
                unsigned lo = An + ((mip * 4 + 2 * ch) * 32 + gdp * 4 + m) * 16u + r1p * 8u;
                unsigned hi = An + ((mip * 4 + 2 * ch + 1) * 32 + gdp * 4 + m) * 16u + r1p * 8u;
                asm volatile("st.shared.v2.f32 [%0], {%1,%2};" :: "r"(lo), "f"(pv0[m]), "f"(pv1[m]));
                asm volatile("st.shared.v2.f32 [%0], {%1,%2};" :: "r"(hi), "f"(pv2[m]), "f"(pv3[m]));
            }
            asm volatile("cp.async.wait_group 0;");
        }
        __syncthreads();
    }

    // epilogue
#pragma unroll
    for (int mm = 0; mm < 4; mm++) {
#pragma unroll
        for (int ni = 0; ni < 4; ni++) {
            const int row = bm + wm * 64 + mm * 16 + gid;
            const int col = bn + wn * 32 + ni * 8 + 2 * tg;
            *(float2*)(C + (size_t)row * OUT_DIM + col) =
                make_float2(acc[mm][ni][0], acc[mm][ni][1]);
            *(float2*)(C + (size_t)(row + 8) * OUT_DIM + col) =
                make_float2(acc[mm][ni][2], acc[mm][ni][3]);
        }
    }
}

// ---------------------------------------------------------------------------
extern "C" void kernel_launch(void* const* d_in, const int* in_sizes, int n_in,
                              void* d_out, int out_size) {
    const float* x  = nullptr;
    const float* bw = nullptr;
    const float* cw = nullptr;
    for (int i = 0; i < n_in; i++) {
        if (in_sizes[i] == B_DIM * IN_DIM)                x  = (const float*)d_in[i];
        else if (in_sizes[i] == OUT_DIM * IN_DIM)         bw = (const float*)d_in[i];
        else if (in_sizes[i] == OUT_DIM * IN_DIM * ORDER) cw = (const float*)d_in[i];
    }
    float* out = (float*)d_out;

    {   // phase 0: fragment-pack W (176*512*2 threads)
        int total = NKT * 512 * 2;
        build_W_kernel<<<(total + 255) / 256, 256>>>(bw, cw);
    }
    {   // phase 1: fused A-gen + tf32 mma.sync GEMM
        cudaFuncSetAttribute(gemm_fused_kernel,
                             cudaFuncAttributeMaxDynamicSharedMemorySize, SMEM_BYTES);
        dim3 grid(OUT_DIM / BN, B_DIM / BM);   // (4, 128)
        gemm_fused_kernel<<<grid, NTHREADS, SMEM_BYTES>>>(x, out);
    }
}